// round 13
// baseline (speedup 1.0000x reference)
#include <cuda_runtime.h>
#include <cuda_fp16.h>
#include <cstdint>
#include <math.h>

#define N_NODES 20000
#define N_EDGES 200000
#define N_GRAPHS 128
#define IN_DIM 256
#define HID 512
#define HEADS 8
#define CH 64
#define LAT 256
#define NEG_SLOPE 0.2f
#define BN_EPS 1e-5f

// ---------------- scratch (static device globals; no allocation) ----------------
__device__ __align__(16) __half d_xh [(size_t)N_NODES * HID];   // GEMM A input; later: final h (fp16)
__device__ __align__(16) __half d_xlh[(size_t)N_NODES * HID];   // xl fp16
__device__ __align__(16) __half d_xrh[(size_t)N_NODES * HID];   // xr fp16
__device__ __align__(16) __half d_wt0[(size_t)1024 * 512];      // [Wl0^T; Wr0^T] fp16 [1024, K0]
__device__ __align__(16) __half d_wt1[(size_t)1024 * 512];      // [Wl1^T; Wr1^T] fp16 [1024, K1]
__device__ __align__(16) int   d_deg[N_NODES];
__device__ int   d_off[N_NODES + 1];
__device__ int   d_cursor[N_NODES];
__device__ int   d_csr[N_EDGES];         // stores SRC node id, grouped by dst
__device__ int   d_goff[N_GRAPHS + 1];

// ---------------- async / ldmatrix helpers ----------------
__device__ __forceinline__ void cp_async16(uint32_t dst, const void* src, int srcBytes) {
    asm volatile("cp.async.cg.shared.global [%0], [%1], 16, %2;"
                 :: "r"(dst), "l"(src), "r"(srcBytes));
}
__device__ __forceinline__ void cp_commit() {
    asm volatile("cp.async.commit_group;");
}
template <int NREM>
__device__ __forceinline__ void cp_wait() {
    asm volatile("cp.async.wait_group %0;" :: "n"(NREM));
}
__device__ __forceinline__ void ldsm_x4(uint32_t (&r)[4], uint32_t addr) {
    asm volatile("ldmatrix.sync.aligned.m8n8.x4.shared.b16 {%0,%1,%2,%3}, [%4];"
                 : "=r"(r[0]), "=r"(r[1]), "=r"(r[2]), "=r"(r[3]) : "r"(addr));
}

// ---------------- small utility kernels ----------------
__global__ void zero_int_kernel(int* p, int n) {
    int i = blockIdx.x * blockDim.x + threadIdx.x;
    if (i < n) p[i] = 0;
}

__global__ void hist_kernel(const int* __restrict__ dst) {
    int e = blockIdx.x * blockDim.x + threadIdx.x;
    if (e < N_EDGES) atomicAdd(&d_deg[dst[e]], 1);
}

// single-block scan: smem-staged, coalesced global access.
__global__ void scan_kernel(const int* __restrict__ batch) {
    extern __shared__ int sdeg[];
    __shared__ int warpsum[33];
    int t = threadIdx.x;

    if (t <= N_GRAPHS) {
        int lo = 0, hi = N_NODES;
        while (lo < hi) {
            int mid = (lo + hi) >> 1;
            if (batch[mid] < t) lo = mid + 1; else hi = mid;
        }
        d_goff[t] = lo;
    }

    for (int i = t; i < N_NODES / 4; i += 1024)
        ((int4*)sdeg)[i] = ((const int4*)d_deg)[i];
    __syncthreads();

    const int base = t * 20;
    int s = 0;
    if (base < N_NODES)
#pragma unroll
        for (int i = 0; i < 20; i++) s += sdeg[base + i];

    int incl = s;
    int lane = t & 31;
#pragma unroll
    for (int o = 1; o < 32; o <<= 1) {
        int u = __shfl_up_sync(0xffffffffu, incl, o);
        if (lane >= o) incl += u;
    }
    if (lane == 31) warpsum[t >> 5] = incl;
    __syncthreads();
    if (t < 32) {
        int w = warpsum[t];
        int wi = w;
#pragma unroll
        for (int o = 1; o < 32; o <<= 1) {
            int u = __shfl_up_sync(0xffffffffu, wi, o);
            if (t >= o) wi += u;
        }
        warpsum[t] = wi - w;
        if (t == 31) warpsum[32] = wi;
    }
    __syncthreads();

    if (base < N_NODES) {
        int run = warpsum[t >> 5] + (incl - s);
#pragma unroll
        for (int i = 0; i < 20; i++) {
            int v = sdeg[base + i];
            sdeg[base + i] = run;
            run += v;
        }
    }
    __syncthreads();

    for (int i = t; i < N_NODES / 4; i += 1024) {
        int4 v = ((int4*)sdeg)[i];
        ((int4*)d_off)[i] = v;
        ((int4*)d_cursor)[i] = v;
    }
    if (t == 0) d_off[N_NODES] = warpsum[32];
}

__global__ void scatter_kernel(const int* __restrict__ src, const int* __restrict__ dst) {
    int e = blockIdx.x * blockDim.x + threadIdx.x;
    if (e < N_EDGES) {
        int p = atomicAdd(&d_cursor[dst[e]], 1);
        d_csr[p] = src[e];
    }
}

// ---------------- fused prep: x->fp16 conversion + 4 weight transposes ----------
#define PREP_CONV_BLOCKS 5000
#define PREP_L0_BLOCKS   256
__global__ __launch_bounds__(256) void prep_kernel(
    const float* __restrict__ x,
    const float* __restrict__ Wl0, const float* __restrict__ Wr0,
    const float* __restrict__ Wl1, const float* __restrict__ Wr1)
{
    int b = blockIdx.x;
    if (b < PREP_CONV_BLOCKS) {
        int i = b * 256 + threadIdx.x;
        float4 v = ((const float4*)x)[i];
        __half2* d = (__half2*)d_xh;
        d[i * 2 + 0] = __floats2half2_rn(v.x, v.y);
        d[i * 2 + 1] = __floats2half2_rn(v.z, v.w);
        return;
    }
    __shared__ float tile[32][33];
    const float* W;
    __half* Wt;
    int K, bx, by;
    if (b < PREP_CONV_BLOCKS + PREP_L0_BLOCKS) {
        int m = b - PREP_CONV_BLOCKS;
        int mat = m >> 7;
        int tb = m & 127;
        bx = tb & 15; by = tb >> 4;
        K = IN_DIM;
        W = mat ? Wr0 : Wl0;
        Wt = d_wt0 + (size_t)mat * 512 * IN_DIM;
    } else {
        int m = b - PREP_CONV_BLOCKS - PREP_L0_BLOCKS;
        int mat = m >> 8;
        int tb = m & 255;
        bx = tb & 15; by = tb >> 4;
        K = HID;
        W = mat ? Wr1 : Wl1;
        Wt = d_wt1 + (size_t)mat * 512 * HID;
    }
    int n0 = bx * 32;
    int k0 = by * 32;
    int tx = threadIdx.x & 31, ty = threadIdx.x >> 5;
#pragma unroll
    for (int j = 0; j < 32; j += 8)
        tile[ty + j][tx] = W[(size_t)(k0 + ty + j) * HID + n0 + tx];
    __syncthreads();
#pragma unroll
    for (int j = 0; j < 32; j += 8)
        Wt[(size_t)(n0 + ty + j) * K + k0 + tx] = __float2half_rn(tile[tx][ty + j]);
}

// ---------------- dual-output fp16 GEMM (2-stage cp.async + ldmatrix) ------------
// 64x128 tiles, 128 threads, 3 CTAs/SM; finer tiles shrink the last-wave tail.
// A: fp16 [N,K].  Bt: fp16 [1024,K] = [Wl^T ; Wr^T].
// cols 0-511 -> Cl (fp16, +biasL); cols 512-1023 -> Cr (fp16, +biasR).
#define GBM 64
#define HBK 32
#define SSTR 40   // halves per smem row (conflict-free for STS.128 and LDSM)

__global__ __launch_bounds__(128, 3) void gemm_dual_kernel(
    const __half* __restrict__ A, const __half* __restrict__ Bt,
    const float* __restrict__ biasL, const float* __restrict__ biasR,
    __half* __restrict__ Cl, __half* __restrict__ Cr,
    int N, int K)
{
    __shared__ __half As[2][GBM * SSTR];     // 64 rows
    __shared__ __half Bs[2][128 * SSTR];     // 128 cols

    const int tid  = threadIdx.x;
    const int lane = tid & 31;
    const int warp = tid >> 5;
    const int wm = warp & 1;        // M half (32 rows each)
    const int wn = warp >> 1;       // N half (64 cols each)
    const int rowBase = blockIdx.y * GBM;
    const int colBase = blockIdx.x * 128;        // 0..1023 over concat
    const int g = lane >> 2;
    const int q = lane & 3;
    const int nt = K / HBK;

    const uint32_t asb = (uint32_t)__cvta_generic_to_shared(&As[0][0]);
    const uint32_t bsb = (uint32_t)__cvta_generic_to_shared(&Bs[0][0]);
    const uint32_t ABUF = GBM * SSTR * 2;        // 5120 B
    const uint32_t BBUF = 128 * SSTR * 2;        // 10240 B

    const int lr = tid >> 2;          // 0..31
    const int lc = (tid & 3) * 8;     // half offset (16B chunks)

    float acc[2][8][4];
#pragma unroll
    for (int i = 0; i < 2; i++)
#pragma unroll
        for (int j = 0; j < 8; j++)
#pragma unroll
            for (int p = 0; p < 4; p++) acc[i][j][p] = 0.0f;

    // prefetch tile 0
    {
#pragma unroll
        for (int i = 0; i < 2; i++) {           // A: 64 rows
            int r = rowBase + lr + 32 * i;
            int rs = (r < N) ? r : 0;
            cp_async16(asb + ((lr + 32 * i) * SSTR + lc) * 2,
                       A + (size_t)rs * K + lc, (r < N) ? 16 : 0);
        }
#pragma unroll
        for (int i = 0; i < 4; i++) {           // B: 128 rows (cols)
            int br = colBase + lr + 32 * i;
            cp_async16(bsb + ((lr + 32 * i) * SSTR + lc) * 2,
                       Bt + (size_t)br * K + lc, 16);
        }
        cp_commit();
    }

    for (int t = 0; t < nt; t++) {
        int buf = t & 1;
        if (t + 1 < nt) {
            int kb = (t + 1) * HBK;
            uint32_t aoff = asb + (buf ^ 1) * ABUF;
            uint32_t boff = bsb + (buf ^ 1) * BBUF;
#pragma unroll
            for (int i = 0; i < 2; i++) {
                int r = rowBase + lr + 32 * i;
                int rs = (r < N) ? r : 0;
                cp_async16(aoff + ((lr + 32 * i) * SSTR + lc) * 2,
                           A + (size_t)rs * K + kb + lc, (r < N) ? 16 : 0);
            }
#pragma unroll
            for (int i = 0; i < 4; i++) {
                int br = colBase + lr + 32 * i;
                cp_async16(boff + ((lr + 32 * i) * SSTR + lc) * 2,
                           Bt + (size_t)br * K + kb + lc, 16);
            }
            cp_commit();
            cp_wait<1>();
        } else {
            cp_wait<0>();
        }
        __syncthreads();

        uint32_t abase = asb + buf * ABUF;
        uint32_t bbase = bsb + buf * BBUF;
        const int arow = wm * 32 + (lane & 15);
        const int ax   = ((lane >> 4) << 3);
        const int bnx  = ((lane >> 4) & 1) * 8 + (lane & 7);
        const int bkx  = ((lane >> 3) & 1) * 8;

#pragma unroll
        for (int kk = 0; kk < 2; kk++) {
            const int kh0 = kk * 16;
            uint32_t af[2][4];
#pragma unroll
            for (int im = 0; im < 2; im++)
                ldsm_x4(af[im], abase + ((arow + im * 16) * SSTR + kh0 + ax) * 2);
            uint32_t bf[8][2];
#pragma unroll
            for (int j = 0; j < 8; j += 2) {
                uint32_t r4[4];
                ldsm_x4(r4, bbase + ((wn * 64 + j * 8 + bnx) * SSTR + kh0 + bkx) * 2);
                bf[j][0] = r4[0]; bf[j][1] = r4[1];
                bf[j + 1][0] = r4[2]; bf[j + 1][1] = r4[3];
            }
#pragma unroll
            for (int im = 0; im < 2; im++)
#pragma unroll
                for (int in = 0; in < 8; in++) {
                    asm volatile(
                        "mma.sync.aligned.m16n8k16.row.col.f32.f16.f16.f32 "
                        "{%0,%1,%2,%3}, {%4,%5,%6,%7}, {%8,%9}, {%0,%1,%2,%3};"
                        : "+f"(acc[im][in][0]), "+f"(acc[im][in][1]),
                          "+f"(acc[im][in][2]), "+f"(acc[im][in][3])
                        : "r"(af[im][0]), "r"(af[im][1]), "r"(af[im][2]), "r"(af[im][3]),
                          "r"(bf[in][0]), "r"(bf[in][1]));
                }
        }
        __syncthreads();
    }

    // ---- epilogue: both halves store fp16 ----
    const bool left = (colBase < HID);
    const float* bias = left ? biasL : biasR;
    __half* C = left ? Cl : Cr;
    const int cadj = left ? colBase : (colBase - HID);
#pragma unroll
    for (int im = 0; im < 2; im++) {
        int r0 = rowBase + wm * 32 + im * 16 + g;
        int r1 = r0 + 8;
#pragma unroll
        for (int in = 0; in < 8; in++) {
            int c = cadj + wn * 64 + in * 8 + 2 * q;
            float b0 = bias[c], b1 = bias[c + 1];
            if (r0 < N)
                *(__half2*)(C + (size_t)r0 * HID + c) =
                    __floats2half2_rn(acc[im][in][0] + b0, acc[im][in][1] + b1);
            if (r1 < N)
                *(__half2*)(C + (size_t)r1 * HID + c) =
                    __floats2half2_rn(acc[im][in][2] + b0, acc[im][in][3] + b1);
        }
    }
}

// ---------------- fused GAT edge+softmax+aggregate (shift-free softmax) ----------
__global__ __launch_bounds__(256) void gat_fused_kernel(
    const __half* __restrict__ xl16, const __half* __restrict__ xr16,
    const float* __restrict__ att, const float* __restrict__ bias,
    __half* __restrict__ out)
{
    int node = (blockIdx.x * blockDim.x + threadIdx.x) >> 5;
    if (node >= N_NODES) return;
    int lane = threadIdx.x & 31;
    int dbase = lane * 16;

    float xrv[16], av[16];
    {
        const uint4* pxr = (const uint4*)(xr16 + (size_t)node * HID + dbase);
        uint4 u0 = pxr[0], u1 = pxr[1];
        const __half2* h0 = (const __half2*)&u0;
        const __half2* h1 = (const __half2*)&u1;
#pragma unroll
        for (int j = 0; j < 4; j++) {
            float2 f0 = __half22float2(h0[j]);
            xrv[j*2+0] = f0.x; xrv[j*2+1] = f0.y;
            float2 f1 = __half22float2(h1[j]);
            xrv[8+j*2+0] = f1.x; xrv[8+j*2+1] = f1.y;
        }
        const float4* pat = (const float4*)(att + dbase);
#pragma unroll
        for (int j = 0; j < 4; j++) {
            float4 b = pat[j];
            av[j*4+0] = b.x; av[j*4+1] = b.y; av[j*4+2] = b.z; av[j*4+3] = b.w;
        }
    }

    float den = 0.0f;
    float acc[16];
#pragma unroll
    for (int j = 0; j < 16; j++) acc[j] = 0.0f;

    int r0 = d_off[node], r1 = d_off[node + 1];
    for (int i = r0; i < r1; i++) {
        int s = d_csr[i];
        const uint4* p = (const uint4*)(xl16 + (size_t)s * HID + dbase);
        uint4 u0 = p[0], u1 = p[1];
        float xlv[16];
        {
            const __half2* h0 = (const __half2*)&u0;
            const __half2* h1 = (const __half2*)&u1;
#pragma unroll
            for (int j = 0; j < 4; j++) {
                float2 f0 = __half22float2(h0[j]);
                xlv[j*2+0] = f0.x; xlv[j*2+1] = f0.y;
                float2 f1 = __half22float2(h1[j]);
                xlv[8+j*2+0] = f1.x; xlv[8+j*2+1] = f1.y;
            }
        }
        float part = 0.0f;
#pragma unroll
        for (int j = 0; j < 16; j++) {
            float f = xlv[j] + xrv[j];
            f = (f > 0.0f) ? f : NEG_SLOPE * f;
            part = fmaf(f, av[j], part);
        }
        part += __shfl_xor_sync(0xffffffffu, part, 1);
        part += __shfl_xor_sync(0xffffffffu, part, 2);

        float pe = __expf(part);
        den += pe;
#pragma unroll
        for (int j = 0; j < 16; j++) acc[j] = fmaf(pe, xlv[j], acc[j]);
    }

    float inv = 1.0f / (den + 1e-16f);
    const float* b = bias + dbase;

    __half2 ov[8];
#pragma unroll
    for (int j = 0; j < 8; j++) {
        float v0 = acc[j*2+0] * inv + b[j*2+0];
        float v1 = acc[j*2+1] * inv + b[j*2+1];
        v0 = (v0 > 0.f) ? v0 : (expf(v0) - 1.0f);
        v1 = (v1 > 0.f) ? v1 : (expf(v1) - 1.0f);
        ov[j] = __floats2half2_rn(v0, v1);
    }
    uint4* o = (uint4*)(out + (size_t)node * HID + dbase);
    o[0] = *(uint4*)&ov[0];
    o[1] = *(uint4*)&ov[4];
}

// ---------------- fused pool + BN + FC head ----------------
__global__ __launch_bounds__(256) void head_kernel(
    const __half* __restrict__ h,
    const float* __restrict__ gamma, const float* __restrict__ beta,
    const float* __restrict__ mean,  const float* __restrict__ var,
    const float* __restrict__ Wfc,   const float* __restrict__ bfc,
    float* __restrict__ out)
{
    int g = blockIdx.x;
    int j = threadIdx.x;
    __shared__ float s[HID];

    int n0 = d_goff[g], n1 = d_goff[g + 1];
    float s0 = 0.0f, s1 = 0.0f;
    for (int n = n0; n < n1; n++) {
        const __half* row = h + (size_t)n * HID;
        s0 += __half2float(row[j]);
        s1 += __half2float(row[j + 256]);
    }
    s[j]       = (s0 - mean[j])       * rsqrtf(var[j] + BN_EPS)       * gamma[j]       + beta[j];
    s[j + 256] = (s1 - mean[j + 256]) * rsqrtf(var[j + 256] + BN_EPS) * gamma[j + 256] + beta[j + 256];
    __syncthreads();

    float acc = bfc[j];
    for (int k = 0; k < HID; k++) acc = fmaf(s[k], Wfc[(size_t)k * LAT + j], acc);
    out[(size_t)g * LAT + j] = acc;
}

// ---------------- launch ----------------
extern "C" void kernel_launch(void* const* d_in, const int* in_sizes, int n_in,
                              void* d_out, int out_size)
{
    const float* x      = (const float*)d_in[0];
    const int*   ei     = (const int*)d_in[1];
    const int*   batch  = (const int*)d_in[2];
    const float* Wl0    = (const float*)d_in[3];
    const float* bl0    = (const float*)d_in[4];
    const float* Wr0    = (const float*)d_in[5];
    const float* br0    = (const float*)d_in[6];
    const float* att0   = (const float*)d_in[7];
    const float* bias0  = (const float*)d_in[8];
    const float* Wl1    = (const float*)d_in[9];
    const float* bl1    = (const float*)d_in[10];
    const float* Wr1    = (const float*)d_in[11];
    const float* br1    = (const float*)d_in[12];
    const float* att1   = (const float*)d_in[13];
    const float* bias1  = (const float*)d_in[14];
    const float* bn_g   = (const float*)d_in[15];
    const float* bn_b   = (const float*)d_in[16];
    const float* bn_m   = (const float*)d_in[17];
    const float* bn_v   = (const float*)d_in[18];
    const float* Wfc    = (const float*)d_in[19];
    const float* bfc    = (const float*)d_in[20];
    float* out = (float*)d_out;

    const int* src = ei;
    const int* dst = ei + N_EDGES;

    __half *p_xh, *p_xlh, *p_xrh, *p_wt0, *p_wt1;
    int *p_deg;
    cudaGetSymbolAddress((void**)&p_xh, d_xh);
    cudaGetSymbolAddress((void**)&p_xlh, d_xlh);
    cudaGetSymbolAddress((void**)&p_xrh, d_xrh);
    cudaGetSymbolAddress((void**)&p_wt0, d_wt0);
    cudaGetSymbolAddress((void**)&p_wt1, d_wt1);
    cudaGetSymbolAddress((void**)&p_deg, d_deg);

    cudaFuncSetAttribute(scan_kernel,
                         cudaFuncAttributeMaxDynamicSharedMemorySize, N_NODES * 4);

    // ---- fork: CSR build chain overlaps prep + layer-0 GEMM ----
    cudaStream_t s2;
    cudaStreamCreateWithFlags(&s2, cudaStreamNonBlocking);
    cudaEvent_t evFork, evJoin;
    cudaEventCreateWithFlags(&evFork, cudaEventDisableTiming);
    cudaEventCreateWithFlags(&evJoin, cudaEventDisableTiming);

    cudaEventRecord(evFork, 0);
    cudaStreamWaitEvent(s2, evFork, 0);
    zero_int_kernel<<<(N_NODES + 255) / 256, 256, 0, s2>>>(p_deg, N_NODES);
    hist_kernel<<<(N_EDGES + 255) / 256, 256, 0, s2>>>(dst);
    scan_kernel<<<1, 1024, N_NODES * 4, s2>>>(batch);
    scatter_kernel<<<(N_EDGES + 255) / 256, 256, 0, s2>>>(src, dst);
    cudaEventRecord(evJoin, s2);

    // ---- main stream: prep + layer-0 GEMM ----
    prep_kernel<<<PREP_CONV_BLOCKS + PREP_L0_BLOCKS + 512, 256>>>(x, Wl0, Wr0, Wl1, Wr1);

    dim3 gemmGrid(8, (N_NODES + GBM - 1) / GBM);
    gemm_dual_kernel<<<gemmGrid, 128>>>(p_xh, p_wt0, bl0, br0, p_xlh, p_xrh, N_NODES, IN_DIM);

    // join CSR chain before the gather kernel
    cudaStreamWaitEvent(0, evJoin, 0);

    // ---- layer 0 gather ----
    gat_fused_kernel<<<(N_NODES * 32 + 255) / 256, 256>>>(p_xlh, p_xrh, att0, bias0, p_xh);

    // ---- layer 1 ----
    gemm_dual_kernel<<<gemmGrid, 128>>>(p_xh, p_wt1, bl1, br1, p_xlh, p_xrh, N_NODES, HID);
    gat_fused_kernel<<<(N_NODES * 32 + 255) / 256, 256>>>(p_xlh, p_xrh, att1, bias1, p_xh);

    // ---- fused pool + BN + FC head ----
    head_kernel<<<N_GRAPHS, LAT>>>(p_xh, bn_g, bn_b, bn_m, bn_v, Wfc, bfc, out);
}

// round 15
// speedup vs baseline: 1.0129x; 1.0129x over previous
#include <cuda_runtime.h>
#include <cuda_fp16.h>
#include <cstdint>
#include <math.h>

#define N_NODES 20000
#define N_EDGES 200000
#define N_GRAPHS 128
#define IN_DIM 256
#define HID 512
#define HEADS 8
#define CH 64
#define LAT 256
#define NEG_SLOPE 0.2f
#define BN_EPS 1e-5f

// ---------------- scratch (static device globals; no allocation) ----------------
__device__ __align__(16) __half d_xh [(size_t)N_NODES * HID];   // layer-1 GEMM A input / final h (fp16)
__device__ __align__(16) __half d_xlh[(size_t)N_NODES * HID];   // xl fp16
__device__ __align__(16) __half d_xrh[(size_t)N_NODES * HID];   // xr fp16
__device__ __align__(16) __half d_wt0[(size_t)1024 * 512];      // [Wl0^T; Wr0^T] fp16 [1024, K0]
__device__ __align__(16) __half d_wt1[(size_t)1024 * 512];      // [Wl1^T; Wr1^T] fp16 [1024, K1]
__device__ __align__(16) int   d_deg[N_NODES];
__device__ int   d_off[N_NODES + 1];
__device__ int   d_cursor[N_NODES];
__device__ int   d_csr[N_EDGES];         // stores SRC node id, grouped by dst
__device__ int   d_goff[N_GRAPHS + 1];

// ---------------- async / ldmatrix helpers ----------------
__device__ __forceinline__ void cp_async16(uint32_t dst, const void* src, int srcBytes) {
    asm volatile("cp.async.cg.shared.global [%0], [%1], 16, %2;"
                 :: "r"(dst), "l"(src), "r"(srcBytes));
}
__device__ __forceinline__ void cp_commit() {
    asm volatile("cp.async.commit_group;");
}
template <int NREM>
__device__ __forceinline__ void cp_wait() {
    asm volatile("cp.async.wait_group %0;" :: "n"(NREM));
}
__device__ __forceinline__ void ldsm_x4(uint32_t (&r)[4], uint32_t addr) {
    asm volatile("ldmatrix.sync.aligned.m8n8.x4.shared.b16 {%0,%1,%2,%3}, [%4];"
                 : "=r"(r[0]), "=r"(r[1]), "=r"(r[2]), "=r"(r[3]) : "r"(addr));
}

// ---------------- small utility kernels ----------------
__global__ void zero_int_kernel(int* p, int n) {
    int i = blockIdx.x * blockDim.x + threadIdx.x;
    if (i < n) p[i] = 0;
}

__global__ void hist_kernel(const int* __restrict__ dst) {
    int e = blockIdx.x * blockDim.x + threadIdx.x;
    if (e < N_EDGES) atomicAdd(&d_deg[dst[e]], 1);
}

// single-block scan: smem-staged, coalesced global access.
__global__ void scan_kernel(const int* __restrict__ batch) {
    extern __shared__ int sdeg[];
    __shared__ int warpsum[33];
    int t = threadIdx.x;

    if (t <= N_GRAPHS) {
        int lo = 0, hi = N_NODES;
        while (lo < hi) {
            int mid = (lo + hi) >> 1;
            if (batch[mid] < t) lo = mid + 1; else hi = mid;
        }
        d_goff[t] = lo;
    }

    for (int i = t; i < N_NODES / 4; i += 1024)
        ((int4*)sdeg)[i] = ((const int4*)d_deg)[i];
    __syncthreads();

    const int base = t * 20;
    int s = 0;
    if (base < N_NODES)
#pragma unroll
        for (int i = 0; i < 20; i++) s += sdeg[base + i];

    int incl = s;
    int lane = t & 31;
#pragma unroll
    for (int o = 1; o < 32; o <<= 1) {
        int u = __shfl_up_sync(0xffffffffu, incl, o);
        if (lane >= o) incl += u;
    }
    if (lane == 31) warpsum[t >> 5] = incl;
    __syncthreads();
    if (t < 32) {
        int w = warpsum[t];
        int wi = w;
#pragma unroll
        for (int o = 1; o < 32; o <<= 1) {
            int u = __shfl_up_sync(0xffffffffu, wi, o);
            if (t >= o) wi += u;
        }
        warpsum[t] = wi - w;
        if (t == 31) warpsum[32] = wi;
    }
    __syncthreads();

    if (base < N_NODES) {
        int run = warpsum[t >> 5] + (incl - s);
#pragma unroll
        for (int i = 0; i < 20; i++) {
            int v = sdeg[base + i];
            sdeg[base + i] = run;
            run += v;
        }
    }
    __syncthreads();

    for (int i = t; i < N_NODES / 4; i += 1024) {
        int4 v = ((int4*)sdeg)[i];
        ((int4*)d_off)[i] = v;
        ((int4*)d_cursor)[i] = v;
    }
    if (t == 0) d_off[N_NODES] = warpsum[32];
}

__global__ void scatter_kernel(const int* __restrict__ src, const int* __restrict__ dst) {
    int e = blockIdx.x * blockDim.x + threadIdx.x;
    if (e < N_EDGES) {
        int p = atomicAdd(&d_cursor[dst[e]], 1);
        d_csr[p] = src[e];
    }
}

// ---------------- prep: 4 weight transposes (conv folded into GEMM0) ------------
#define PREP_L0_BLOCKS   256
__global__ __launch_bounds__(256) void prep_kernel(
    const float* __restrict__ Wl0, const float* __restrict__ Wr0,
    const float* __restrict__ Wl1, const float* __restrict__ Wr1)
{
    int b = blockIdx.x;
    __shared__ float tile[32][33];
    const float* W;
    __half* Wt;
    int K, bx, by;
    if (b < PREP_L0_BLOCKS) {
        int mat = b >> 7;
        int tb = b & 127;
        bx = tb & 15; by = tb >> 4;
        K = IN_DIM;
        W = mat ? Wr0 : Wl0;
        Wt = d_wt0 + (size_t)mat * 512 * IN_DIM;
    } else {
        int m = b - PREP_L0_BLOCKS;
        int mat = m >> 8;
        int tb = m & 255;
        bx = tb & 15; by = tb >> 4;
        K = HID;
        W = mat ? Wr1 : Wl1;
        Wt = d_wt1 + (size_t)mat * 512 * HID;
    }
    int n0 = bx * 32;
    int k0 = by * 32;
    int tx = threadIdx.x & 31, ty = threadIdx.x >> 5;
#pragma unroll
    for (int j = 0; j < 32; j += 8)
        tile[ty + j][tx] = W[(size_t)(k0 + ty + j) * HID + n0 + tx];
    __syncthreads();
#pragma unroll
    for (int j = 0; j < 32; j += 8)
        Wt[(size_t)(n0 + ty + j) * K + k0 + tx] = __float2half_rn(tile[tx][ty + j]);
}

// ---------------- dual-output fp16 GEMM (2-stage cp.async + ldmatrix) ------------
// R12-proven shape: 128 threads, occupancy 2, 128x128 tiles.
// AF32=true: A is fp32, converted to fp16 in-register during the load phase
//            (folds the x->fp16 prep pass into GEMM0).
// Bt: fp16 [1024,K] = [Wl^T ; Wr^T].
// cols 0-511 -> Cl (fp16, +biasL); cols 512-1023 -> Cr (fp16, +biasR).
#define GBM 128
#define HBK 32
#define SSTR 40   // halves per smem row (conflict-free for STS.128 and LDSM)

template <bool AF32>
__global__ __launch_bounds__(128, 2) void gemm_dual_kernel(
    const void* __restrict__ Ain, const __half* __restrict__ Bt,
    const float* __restrict__ biasL, const float* __restrict__ biasR,
    __half* __restrict__ Cl, __half* __restrict__ Cr,
    int N, int K)
{
    __shared__ __half As[2][GBM * SSTR];
    __shared__ __half Bs[2][GBM * SSTR];

    const __half* A16 = (const __half*)Ain;
    const float*  A32 = (const float*)Ain;

    const int tid  = threadIdx.x;
    const int lane = tid & 31;
    const int warp = tid >> 5;
    const int wm = warp & 1;
    const int wn = warp >> 1;
    const int rowBase = blockIdx.y * GBM;
    const int colBase = blockIdx.x * 128;        // 0..1023 over concat
    const int g = lane >> 2;
    const int q = lane & 3;
    const int nt = K / HBK;

    const uint32_t asb = (uint32_t)__cvta_generic_to_shared(&As[0][0]);
    const uint32_t bsb = (uint32_t)__cvta_generic_to_shared(&Bs[0][0]);
    const uint32_t BUFB = GBM * SSTR * 2;        // bytes per buffer

    const int lr = tid >> 2;          // 0..31
    const int lc = (tid & 3) * 8;     // element offset within BK

    float acc[4][8][4];
#pragma unroll
    for (int i = 0; i < 4; i++)
#pragma unroll
        for (int j = 0; j < 8; j++)
#pragma unroll
            for (int p = 0; p < 4; p++) acc[i][j][p] = 0.0f;

    // A loader: cp.async (fp16) or LDG+cvt+STS (fp32)
    auto load_A = [&](int kb, int buf) {
#pragma unroll
        for (int i = 0; i < 4; i++) {
            int row = lr + 32 * i;
            int r = rowBase + row;
            if (AF32) {
                uint4 hv = make_uint4(0u, 0u, 0u, 0u);
                if (r < N) {
                    const float4* pa = (const float4*)(A32 + (size_t)r * K + kb + lc);
                    float4 v0 = pa[0], v1 = pa[1];
                    __half2 h0 = __floats2half2_rn(v0.x, v0.y);
                    __half2 h1 = __floats2half2_rn(v0.z, v0.w);
                    __half2 h2 = __floats2half2_rn(v1.x, v1.y);
                    __half2 h3 = __floats2half2_rn(v1.z, v1.w);
                    hv.x = *(uint32_t*)&h0; hv.y = *(uint32_t*)&h1;
                    hv.z = *(uint32_t*)&h2; hv.w = *(uint32_t*)&h3;
                }
                *(uint4*)&As[buf][row * SSTR + lc] = hv;
            } else {
                int rs = (r < N) ? r : 0;
                cp_async16(asb + buf * BUFB + (row * SSTR + lc) * 2,
                           A16 + (size_t)rs * K + kb + lc, (r < N) ? 16 : 0);
            }
        }
    };
    auto load_B = [&](int kb, int buf) {
#pragma unroll
        for (int i = 0; i < 4; i++) {
            int br = colBase + lr + 32 * i;
            cp_async16(bsb + buf * BUFB + ((lr + 32 * i) * SSTR + lc) * 2,
                       Bt + (size_t)br * K + kb + lc, 16);
        }
    };

    // prefetch tile 0
    load_A(0, 0);
    load_B(0, 0);
    cp_commit();

    for (int t = 0; t < nt; t++) {
        int buf = t & 1;
        if (t + 1 < nt) {
            int kb = (t + 1) * HBK;
            load_A(kb, buf ^ 1);
            load_B(kb, buf ^ 1);
            cp_commit();
            cp_wait<1>();
        } else {
            cp_wait<0>();
        }
        __syncthreads();

        uint32_t abase = asb + buf * BUFB;
        uint32_t bbase = bsb + buf * BUFB;
        const int arow = wm * 64 + (lane & 15);
        const int ax   = ((lane >> 4) << 3);
        const int bnx  = ((lane >> 4) & 1) * 8 + (lane & 7);
        const int bkx  = ((lane >> 3) & 1) * 8;

#pragma unroll
        for (int kk = 0; kk < 2; kk++) {
            const int kh0 = kk * 16;
            uint32_t af[4][4];
#pragma unroll
            for (int im = 0; im < 4; im++)
                ldsm_x4(af[im], abase + ((arow + im * 16) * SSTR + kh0 + ax) * 2);
            uint32_t bf[8][2];
#pragma unroll
            for (int j = 0; j < 8; j += 2) {
                uint32_t r4[4];
                ldsm_x4(r4, bbase + ((wn * 64 + j * 8 + bnx) * SSTR + kh0 + bkx) * 2);
                bf[j][0] = r4[0]; bf[j][1] = r4[1];
                bf[j + 1][0] = r4[2]; bf[j + 1][1] = r4[3];
            }
#pragma unroll
            for (int im = 0; im < 4; im++)
#pragma unroll
                for (int in = 0; in < 8; in++) {
                    asm volatile(
                        "mma.sync.aligned.m16n8k16.row.col.f32.f16.f16.f32 "
                        "{%0,%1,%2,%3}, {%4,%5,%6,%7}, {%8,%9}, {%0,%1,%2,%3};"
                        : "+f"(acc[im][in][0]), "+f"(acc[im][in][1]),
                          "+f"(acc[im][in][2]), "+f"(acc[im][in][3])
                        : "r"(af[im][0]), "r"(af[im][1]), "r"(af[im][2]), "r"(af[im][3]),
                          "r"(bf[in][0]), "r"(bf[in][1]));
                }
        }
        __syncthreads();
    }

    // ---- epilogue: both halves store fp16 ----
    const bool left = (colBase < HID);
    const float* bias = left ? biasL : biasR;
    __half* C = left ? Cl : Cr;
    const int cadj = left ? colBase : (colBase - HID);
#pragma unroll
    for (int im = 0; im < 4; im++) {
        int r0 = rowBase + wm * 64 + im * 16 + g;
        int r1 = r0 + 8;
#pragma unroll
        for (int in = 0; in < 8; in++) {
            int c = cadj + wn * 64 + in * 8 + 2 * q;
            float b0 = bias[c], b1 = bias[c + 1];
            if (r0 < N)
                *(__half2*)(C + (size_t)r0 * HID + c) =
                    __floats2half2_rn(acc[im][in][0] + b0, acc[im][in][1] + b1);
            if (r1 < N)
                *(__half2*)(C + (size_t)r1 * HID + c) =
                    __floats2half2_rn(acc[im][in][2] + b0, acc[im][in][3] + b1);
        }
    }
}

// ---------------- fused GAT edge+softmax+aggregate (shift-free softmax) ----------
__global__ __launch_bounds__(256) void gat_fused_kernel(
    const __half* __restrict__ xl16, const __half* __restrict__ xr16,
    const float* __restrict__ att, const float* __restrict__ bias,
    __half* __restrict__ out)
{
    int node = (blockIdx.x * blockDim.x + threadIdx.x) >> 5;
    if (node >= N_NODES) return;
    int lane = threadIdx.x & 31;
    int dbase = lane * 16;

    float xrv[16], av[16];
    {
        const uint4* pxr = (const uint4*)(xr16 + (size_t)node * HID + dbase);
        uint4 u0 = pxr[0], u1 = pxr[1];
        const __half2* h0 = (const __half2*)&u0;
        const __half2* h1 = (const __half2*)&u1;
#pragma unroll
        for (int j = 0; j < 4; j++) {
            float2 f0 = __half22float2(h0[j]);
            xrv[j*2+0] = f0.x; xrv[j*2+1] = f0.y;
            float2 f1 = __half22float2(h1[j]);
            xrv[8+j*2+0] = f1.x; xrv[8+j*2+1] = f1.y;
        }
        const float4* pat = (const float4*)(att + dbase);
#pragma unroll
        for (int j = 0; j < 4; j++) {
            float4 b = pat[j];
            av[j*4+0] = b.x; av[j*4+1] = b.y; av[j*4+2] = b.z; av[j*4+3] = b.w;
        }
    }

    float den = 0.0f;
    float acc[16];
#pragma unroll
    for (int j = 0; j < 16; j++) acc[j] = 0.0f;

    int r0 = d_off[node], r1 = d_off[node + 1];
    for (int i = r0; i < r1; i++) {
        int s = d_csr[i];
        const uint4* p = (const uint4*)(xl16 + (size_t)s * HID + dbase);
        uint4 u0 = p[0], u1 = p[1];
        float xlv[16];
        {
            const __half2* h0 = (const __half2*)&u0;
            const __half2* h1 = (const __half2*)&u1;
#pragma unroll
            for (int j = 0; j < 4; j++) {
                float2 f0 = __half22float2(h0[j]);
                xlv[j*2+0] = f0.x; xlv[j*2+1] = f0.y;
                float2 f1 = __half22float2(h1[j]);
                xlv[8+j*2+0] = f1.x; xlv[8+j*2+1] = f1.y;
            }
        }
        float part = 0.0f;
#pragma unroll
        for (int j = 0; j < 16; j++) {
            float f = xlv[j] + xrv[j];
            f = (f > 0.0f) ? f : NEG_SLOPE * f;
            part = fmaf(f, av[j], part);
        }
        part += __shfl_xor_sync(0xffffffffu, part, 1);
        part += __shfl_xor_sync(0xffffffffu, part, 2);

        float pe = __expf(part);
        den += pe;
#pragma unroll
        for (int j = 0; j < 16; j++) acc[j] = fmaf(pe, xlv[j], acc[j]);
    }

    float inv = 1.0f / (den + 1e-16f);
    const float* b = bias + dbase;

    __half2 ov[8];
#pragma unroll
    for (int j = 0; j < 8; j++) {
        float v0 = acc[j*2+0] * inv + b[j*2+0];
        float v1 = acc[j*2+1] * inv + b[j*2+1];
        v0 = (v0 > 0.f) ? v0 : (expf(v0) - 1.0f);
        v1 = (v1 > 0.f) ? v1 : (expf(v1) - 1.0f);
        ov[j] = __floats2half2_rn(v0, v1);
    }
    uint4* o = (uint4*)(out + (size_t)node * HID + dbase);
    o[0] = *(uint4*)&ov[0];
    o[1] = *(uint4*)&ov[4];
}

// ---------------- fused pool + BN + FC head ----------------
__global__ __launch_bounds__(256) void head_kernel(
    const __half* __restrict__ h,
    const float* __restrict__ gamma, const float* __restrict__ beta,
    const float* __restrict__ mean,  const float* __restrict__ var,
    const float* __restrict__ Wfc,   const float* __restrict__ bfc,
    float* __restrict__ out)
{
    int g = blockIdx.x;
    int j = threadIdx.x;
    __shared__ float s[HID];

    int n0 = d_goff[g], n1 = d_goff[g + 1];
    float s0 = 0.0f, s1 = 0.0f;
    for (int n = n0; n < n1; n++) {
        const __half* row = h + (size_t)n * HID;
        s0 += __half2float(row[j]);
        s1 += __half2float(row[j + 256]);
    }
    s[j]       = (s0 - mean[j])       * rsqrtf(var[j] + BN_EPS)       * gamma[j]       + beta[j];
    s[j + 256] = (s1 - mean[j + 256]) * rsqrtf(var[j + 256] + BN_EPS) * gamma[j + 256] + beta[j + 256];
    __syncthreads();

    float acc = bfc[j];
    for (int k = 0; k < HID; k++) acc = fmaf(s[k], Wfc[(size_t)k * LAT + j], acc);
    out[(size_t)g * LAT + j] = acc;
}

// ---------------- launch ----------------
extern "C" void kernel_launch(void* const* d_in, const int* in_sizes, int n_in,
                              void* d_out, int out_size)
{
    const float* x      = (const float*)d_in[0];
    const int*   ei     = (const int*)d_in[1];
    const int*   batch  = (const int*)d_in[2];
    const float* Wl0    = (const float*)d_in[3];
    const float* bl0    = (const float*)d_in[4];
    const float* Wr0    = (const float*)d_in[5];
    const float* br0    = (const float*)d_in[6];
    const float* att0   = (const float*)d_in[7];
    const float* bias0  = (const float*)d_in[8];
    const float* Wl1    = (const float*)d_in[9];
    const float* bl1    = (const float*)d_in[10];
    const float* Wr1    = (const float*)d_in[11];
    const float* br1    = (const float*)d_in[12];
    const float* att1   = (const float*)d_in[13];
    const float* bias1  = (const float*)d_in[14];
    const float* bn_g   = (const float*)d_in[15];
    const float* bn_b   = (const float*)d_in[16];
    const float* bn_m   = (const float*)d_in[17];
    const float* bn_v   = (const float*)d_in[18];
    const float* Wfc    = (const float*)d_in[19];
    const float* bfc    = (const float*)d_in[20];
    float* out = (float*)d_out;

    const int* src = ei;
    const int* dst = ei + N_EDGES;

    __half *p_xh, *p_xlh, *p_xrh, *p_wt0, *p_wt1;
    int *p_deg;
    cudaGetSymbolAddress((void**)&p_xh, d_xh);
    cudaGetSymbolAddress((void**)&p_xlh, d_xlh);
    cudaGetSymbolAddress((void**)&p_xrh, d_xrh);
    cudaGetSymbolAddress((void**)&p_wt0, d_wt0);
    cudaGetSymbolAddress((void**)&p_wt1, d_wt1);
    cudaGetSymbolAddress((void**)&p_deg, d_deg);

    // once-only resources (created during the pre-capture correctness call;
    // never re-created, so no allocations during capture/teardown)
    static bool inited = false;
    static cudaStream_t s2;
    static cudaEvent_t evFork, evJoin;
    if (!inited) {
        cudaStreamCreateWithFlags(&s2, cudaStreamNonBlocking);
        cudaEventCreateWithFlags(&evFork, cudaEventDisableTiming);
        cudaEventCreateWithFlags(&evJoin, cudaEventDisableTiming);
        cudaFuncSetAttribute(scan_kernel,
                             cudaFuncAttributeMaxDynamicSharedMemorySize, N_NODES * 4);
        inited = true;
    }

    // ---- fork: CSR build chain overlaps prep + layer-0 GEMM ----
    cudaEventRecord(evFork, 0);
    cudaStreamWaitEvent(s2, evFork, 0);
    zero_int_kernel<<<(N_NODES + 255) / 256, 256, 0, s2>>>(p_deg, N_NODES);
    hist_kernel<<<(N_EDGES + 255) / 256, 256, 0, s2>>>(dst);
    scan_kernel<<<1, 1024, N_NODES * 4, s2>>>(batch);
    scatter_kernel<<<(N_EDGES + 255) / 256, 256, 0, s2>>>(src, dst);
    cudaEventRecord(evJoin, s2);

    // ---- main stream: weight transposes + layer-0 GEMM (A fp32, in-reg cvt) ----
    prep_kernel<<<PREP_L0_BLOCKS + 512, 256>>>(Wl0, Wr0, Wl1, Wr1);

    dim3 gemmGrid(8, (N_NODES + GBM - 1) / GBM);
    gemm_dual_kernel<true><<<gemmGrid, 128>>>(x, p_wt0, bl0, br0, p_xlh, p_xrh, N_NODES, IN_DIM);

    // join CSR chain before the gather kernel
    cudaStreamWaitEvent(0, evJoin, 0);

    // ---- layer 0 gather ----
    gat_fused_kernel<<<(N_NODES * 32 + 255) / 256, 256>>>(p_xlh, p_xrh, att0, bias0, p_xh);

    // ---- layer 1 ----
    gemm_dual_kernel<false><<<gemmGrid, 128>>>(p_xh, p_wt1, bl1, br1, p_xlh, p_xrh, N_NODES, HID);
    gat_fused_kernel<<<(N_NODES * 32 + 255) / 256, 256>>>(p_xlh, p_xrh, att1, bias1, p_xh);

    // ---- fused pool + BN + FC head ----
    head_kernel<<<N_GRAPHS, LAT>>>(p_xh, bn_g, bn_b, bn_m, bn_v, Wfc, bfc, out);
}

// round 16
// speedup vs baseline: 1.0656x; 1.0521x over previous
#include <cuda_runtime.h>
#include <cuda_fp16.h>
#include <cstdint>
#include <math.h>

#define N_NODES 20000
#define N_EDGES 200000
#define N_GRAPHS 128
#define IN_DIM 256
#define HID 512
#define HEADS 8
#define CH 64
#define LAT 256
#define NEG_SLOPE 0.2f
#define BN_EPS 1e-5f

// ---------------- scratch (static device globals; no allocation) ----------------
__device__ __align__(16) __half d_xh [(size_t)N_NODES * HID];   // GEMM A input; later: final h (fp16)
__device__ __align__(16) __half d_xlh[(size_t)N_NODES * HID];   // xl fp16
__device__ __align__(16) __half d_xrh[(size_t)N_NODES * HID];   // xr fp16
__device__ __align__(16) __half d_wt0[(size_t)1024 * 512];      // [Wl0^T; Wr0^T] fp16 [1024, K0]
__device__ __align__(16) __half d_wt1[(size_t)1024 * 512];      // [Wl1^T; Wr1^T] fp16 [1024, K1]
__device__ __align__(16) int   d_deg[N_NODES];
__device__ int   d_off[N_NODES + 1];
__device__ int   d_cursor[N_NODES];
__device__ int   d_csr[N_EDGES];         // stores SRC node id, grouped by dst
__device__ int   d_goff[N_GRAPHS + 1];

// ---------------- async / ldmatrix helpers ----------------
__device__ __forceinline__ void cp_async16(uint32_t dst, const void* src, int srcBytes) {
    asm volatile("cp.async.cg.shared.global [%0], [%1], 16, %2;"
                 :: "r"(dst), "l"(src), "r"(srcBytes));
}
__device__ __forceinline__ void cp_commit() {
    asm volatile("cp.async.commit_group;");
}
template <int NREM>
__device__ __forceinline__ void cp_wait() {
    asm volatile("cp.async.wait_group %0;" :: "n"(NREM));
}
__device__ __forceinline__ void ldsm_x4(uint32_t (&r)[4], uint32_t addr) {
    asm volatile("ldmatrix.sync.aligned.m8n8.x4.shared.b16 {%0,%1,%2,%3}, [%4];"
                 : "=r"(r[0]), "=r"(r[1]), "=r"(r[2]), "=r"(r[3]) : "r"(addr));
}

// ---------------- small utility kernels ----------------
__global__ void zero_int_kernel(int* p, int n) {
    int i = blockIdx.x * blockDim.x + threadIdx.x;
    if (i < n) p[i] = 0;
}

__global__ void hist_kernel(const int* __restrict__ dst) {
    int e = blockIdx.x * blockDim.x + threadIdx.x;
    if (e < N_EDGES) atomicAdd(&d_deg[dst[e]], 1);
}

// single-block scan: smem-staged, coalesced global access.
__global__ void scan_kernel(const int* __restrict__ batch) {
    extern __shared__ int sdeg[];
    __shared__ int warpsum[33];
    int t = threadIdx.x;

    if (t <= N_GRAPHS) {
        int lo = 0, hi = N_NODES;
        while (lo < hi) {
            int mid = (lo + hi) >> 1;
            if (batch[mid] < t) lo = mid + 1; else hi = mid;
        }
        d_goff[t] = lo;
    }

    for (int i = t; i < N_NODES / 4; i += 1024)
        ((int4*)sdeg)[i] = ((const int4*)d_deg)[i];
    __syncthreads();

    const int base = t * 20;
    int s = 0;
    if (base < N_NODES)
#pragma unroll
        for (int i = 0; i < 20; i++) s += sdeg[base + i];

    int incl = s;
    int lane = t & 31;
#pragma unroll
    for (int o = 1; o < 32; o <<= 1) {
        int u = __shfl_up_sync(0xffffffffu, incl, o);
        if (lane >= o) incl += u;
    }
    if (lane == 31) warpsum[t >> 5] = incl;
    __syncthreads();
    if (t < 32) {
        int w = warpsum[t];
        int wi = w;
#pragma unroll
        for (int o = 1; o < 32; o <<= 1) {
            int u = __shfl_up_sync(0xffffffffu, wi, o);
            if (t >= o) wi += u;
        }
        warpsum[t] = wi - w;
        if (t == 31) warpsum[32] = wi;
    }
    __syncthreads();

    if (base < N_NODES) {
        int run = warpsum[t >> 5] + (incl - s);
#pragma unroll
        for (int i = 0; i < 20; i++) {
            int v = sdeg[base + i];
            sdeg[base + i] = run;
            run += v;
        }
    }
    __syncthreads();

    for (int i = t; i < N_NODES / 4; i += 1024) {
        int4 v = ((int4*)sdeg)[i];
        ((int4*)d_off)[i] = v;
        ((int4*)d_cursor)[i] = v;
    }
    if (t == 0) d_off[N_NODES] = warpsum[32];
}

__global__ void scatter_kernel(const int* __restrict__ src, const int* __restrict__ dst) {
    int e = blockIdx.x * blockDim.x + threadIdx.x;
    if (e < N_EDGES) {
        int p = atomicAdd(&d_cursor[dst[e]], 1);
        d_csr[p] = src[e];
    }
}

// ---------------- shared weight-transpose body ----------------
__device__ __forceinline__ void wtrans_tile(const float* W, __half* Wt, int K, int bx, int by) {
    __shared__ float tile[32][33];
    int n0 = bx * 32;
    int k0 = by * 32;
    int tx = threadIdx.x & 31, ty = threadIdx.x >> 5;
#pragma unroll
    for (int j = 0; j < 32; j += 8)
        tile[ty + j][tx] = W[(size_t)(k0 + ty + j) * HID + n0 + tx];
    __syncthreads();
#pragma unroll
    for (int j = 0; j < 32; j += 8)
        Wt[(size_t)(n0 + ty + j) * K + k0 + tx] = __float2half_rn(tile[tx][ty + j]);
}

// prep0: x->fp16 conversion + layer-0 weight transposes (critical path for GEMM0)
#define PREP_CONV_BLOCKS 5000
__global__ __launch_bounds__(256) void prep0_kernel(
    const float* __restrict__ x,
    const float* __restrict__ Wl0, const float* __restrict__ Wr0)
{
    int b = blockIdx.x;
    if (b < PREP_CONV_BLOCKS) {
        int i = b * 256 + threadIdx.x;
        float4 v = ((const float4*)x)[i];
        __half2* d = (__half2*)d_xh;
        d[i * 2 + 0] = __floats2half2_rn(v.x, v.y);
        d[i * 2 + 1] = __floats2half2_rn(v.z, v.w);
        return;
    }
    int m = b - PREP_CONV_BLOCKS;          // 256 blocks: 2 mats x (16x8) tiles
    int mat = m >> 7;
    int tb = m & 127;
    wtrans_tile(mat ? Wr0 : Wl0, d_wt0 + (size_t)mat * 512 * IN_DIM,
                IN_DIM, tb & 15, tb >> 4);
}

// prep1: layer-1 weight transposes (runs on the fork stream; needed by GEMM1 only)
__global__ __launch_bounds__(256) void prep1_kernel(
    const float* __restrict__ Wl1, const float* __restrict__ Wr1)
{
    int m = blockIdx.x;                    // 512 blocks: 2 mats x (16x16) tiles
    int mat = m >> 8;
    int tb = m & 255;
    wtrans_tile(mat ? Wr1 : Wl1, d_wt1 + (size_t)mat * 512 * HID,
                HID, tb & 15, tb >> 4);
}

// ---------------- dual-output fp16 GEMM (2-stage cp.async + ldmatrix) ------------
// R12-proven: 128 threads, occupancy 2, 128x128 tiles.
// A: fp16 [N,K].  Bt: fp16 [1024,K] = [Wl^T ; Wr^T].
// cols 0-511 -> Cl (fp16, +biasL); cols 512-1023 -> Cr (fp16, +biasR).
#define GBM 128
#define HBK 32
#define SSTR 40   // halves per smem row (conflict-free for STS.128 and LDSM)

__global__ __launch_bounds__(128, 2) void gemm_dual_kernel(
    const __half* __restrict__ A, const __half* __restrict__ Bt,
    const float* __restrict__ biasL, const float* __restrict__ biasR,
    __half* __restrict__ Cl, __half* __restrict__ Cr,
    int N, int K)
{
    __shared__ __half As[2][GBM * SSTR];
    __shared__ __half Bs[2][GBM * SSTR];

    const int tid  = threadIdx.x;
    const int lane = tid & 31;
    const int warp = tid >> 5;
    const int wm = warp & 1;
    const int wn = warp >> 1;
    const int rowBase = blockIdx.y * GBM;
    const int colBase = blockIdx.x * 128;        // 0..1023 over concat
    const int g = lane >> 2;
    const int q = lane & 3;
    const int nt = K / HBK;

    const uint32_t asb = (uint32_t)__cvta_generic_to_shared(&As[0][0]);
    const uint32_t bsb = (uint32_t)__cvta_generic_to_shared(&Bs[0][0]);
    const uint32_t BUFB = GBM * SSTR * 2;        // bytes per buffer

    const int lr = tid >> 2;          // 0..31
    const int lc = (tid & 3) * 8;     // half offset (16B chunks)

    float acc[4][8][4];
#pragma unroll
    for (int i = 0; i < 4; i++)
#pragma unroll
        for (int j = 0; j < 8; j++)
#pragma unroll
            for (int p = 0; p < 4; p++) acc[i][j][p] = 0.0f;

    // prefetch tile 0
    {
#pragma unroll
        for (int i = 0; i < 4; i++) {
            int r = rowBase + lr + 32 * i;
            int rs = (r < N) ? r : 0;
            cp_async16(asb + ((lr + 32 * i) * SSTR + lc) * 2,
                       A + (size_t)rs * K + lc, (r < N) ? 16 : 0);
            int br = colBase + lr + 32 * i;
            cp_async16(bsb + ((lr + 32 * i) * SSTR + lc) * 2,
                       Bt + (size_t)br * K + lc, 16);
        }
        cp_commit();
    }

    for (int t = 0; t < nt; t++) {
        int buf = t & 1;
        if (t + 1 < nt) {
            int kb = (t + 1) * HBK;
            uint32_t aoff = asb + (buf ^ 1) * BUFB;
            uint32_t boff = bsb + (buf ^ 1) * BUFB;
#pragma unroll
            for (int i = 0; i < 4; i++) {
                int r = rowBase + lr + 32 * i;
                int rs = (r < N) ? r : 0;
                cp_async16(aoff + ((lr + 32 * i) * SSTR + lc) * 2,
                           A + (size_t)rs * K + kb + lc, (r < N) ? 16 : 0);
                int br = colBase + lr + 32 * i;
                cp_async16(boff + ((lr + 32 * i) * SSTR + lc) * 2,
                           Bt + (size_t)br * K + kb + lc, 16);
            }
            cp_commit();
            cp_wait<1>();
        } else {
            cp_wait<0>();
        }
        __syncthreads();

        uint32_t abase = asb + buf * BUFB;
        uint32_t bbase = bsb + buf * BUFB;
        const int arow = wm * 64 + (lane & 15);
        const int ax   = ((lane >> 4) << 3);
        const int bnx  = ((lane >> 4) & 1) * 8 + (lane & 7);
        const int bkx  = ((lane >> 3) & 1) * 8;

#pragma unroll
        for (int kk = 0; kk < 2; kk++) {
            const int kh0 = kk * 16;
            uint32_t af[4][4];
#pragma unroll
            for (int im = 0; im < 4; im++)
                ldsm_x4(af[im], abase + ((arow + im * 16) * SSTR + kh0 + ax) * 2);
            uint32_t bf[8][2];
#pragma unroll
            for (int j = 0; j < 8; j += 2) {
                uint32_t r4[4];
                ldsm_x4(r4, bbase + ((wn * 64 + j * 8 + bnx) * SSTR + kh0 + bkx) * 2);
                bf[j][0] = r4[0]; bf[j][1] = r4[1];
                bf[j + 1][0] = r4[2]; bf[j + 1][1] = r4[3];
            }
#pragma unroll
            for (int im = 0; im < 4; im++)
#pragma unroll
                for (int in = 0; in < 8; in++) {
                    asm volatile(
                        "mma.sync.aligned.m16n8k16.row.col.f32.f16.f16.f32 "
                        "{%0,%1,%2,%3}, {%4,%5,%6,%7}, {%8,%9}, {%0,%1,%2,%3};"
                        : "+f"(acc[im][in][0]), "+f"(acc[im][in][1]),
                          "+f"(acc[im][in][2]), "+f"(acc[im][in][3])
                        : "r"(af[im][0]), "r"(af[im][1]), "r"(af[im][2]), "r"(af[im][3]),
                          "r"(bf[in][0]), "r"(bf[in][1]));
                }
        }
        __syncthreads();
    }

    // ---- epilogue: both halves store fp16; bias hoisted out of the im loop ----
    const bool left = (colBase < HID);
    const float* bias = left ? biasL : biasR;
    __half* C = left ? Cl : Cr;
    const int cadj = left ? colBase : (colBase - HID);

    float bv0[8], bv1[8];
#pragma unroll
    for (int in = 0; in < 8; in++) {
        int c = cadj + wn * 64 + in * 8 + 2 * q;
        bv0[in] = bias[c];
        bv1[in] = bias[c + 1];
    }
#pragma unroll
    for (int im = 0; im < 4; im++) {
        int r0 = rowBase + wm * 64 + im * 16 + g;
        int r1 = r0 + 8;
#pragma unroll
        for (int in = 0; in < 8; in++) {
            int c = cadj + wn * 64 + in * 8 + 2 * q;
            if (r0 < N)
                *(__half2*)(C + (size_t)r0 * HID + c) =
                    __floats2half2_rn(acc[im][in][0] + bv0[in], acc[im][in][1] + bv1[in]);
            if (r1 < N)
                *(__half2*)(C + (size_t)r1 * HID + c) =
                    __floats2half2_rn(acc[im][in][2] + bv0[in], acc[im][in][3] + bv1[in]);
        }
    }
}

// ---------------- fused GAT edge+softmax+aggregate (shift-free softmax) ----------
__global__ __launch_bounds__(256) void gat_fused_kernel(
    const __half* __restrict__ xl16, const __half* __restrict__ xr16,
    const float* __restrict__ att, const float* __restrict__ bias,
    __half* __restrict__ out)
{
    int node = (blockIdx.x * blockDim.x + threadIdx.x) >> 5;
    if (node >= N_NODES) return;
    int lane = threadIdx.x & 31;
    int dbase = lane * 16;

    float xrv[16], av[16];
    {
        const uint4* pxr = (const uint4*)(xr16 + (size_t)node * HID + dbase);
        uint4 u0 = pxr[0], u1 = pxr[1];
        const __half2* h0 = (const __half2*)&u0;
        const __half2* h1 = (const __half2*)&u1;
#pragma unroll
        for (int j = 0; j < 4; j++) {
            float2 f0 = __half22float2(h0[j]);
            xrv[j*2+0] = f0.x; xrv[j*2+1] = f0.y;
            float2 f1 = __half22float2(h1[j]);
            xrv[8+j*2+0] = f1.x; xrv[8+j*2+1] = f1.y;
        }
        const float4* pat = (const float4*)(att + dbase);
#pragma unroll
        for (int j = 0; j < 4; j++) {
            float4 b = pat[j];
            av[j*4+0] = b.x; av[j*4+1] = b.y; av[j*4+2] = b.z; av[j*4+3] = b.w;
        }
    }

    float den = 0.0f;
    float acc[16];
#pragma unroll
    for (int j = 0; j < 16; j++) acc[j] = 0.0f;

    int r0 = d_off[node], r1 = d_off[node + 1];
    for (int i = r0; i < r1; i++) {
        int s = d_csr[i];
        const uint4* p = (const uint4*)(xl16 + (size_t)s * HID + dbase);
        uint4 u0 = p[0], u1 = p[1];
        float xlv[16];
        {
            const __half2* h0 = (const __half2*)&u0;
            const __half2* h1 = (const __half2*)&u1;
#pragma unroll
            for (int j = 0; j < 4; j++) {
                float2 f0 = __half22float2(h0[j]);
                xlv[j*2+0] = f0.x; xlv[j*2+1] = f0.y;
                float2 f1 = __half22float2(h1[j]);
                xlv[8+j*2+0] = f1.x; xlv[8+j*2+1] = f1.y;
            }
        }
        float part = 0.0f;
#pragma unroll
        for (int j = 0; j < 16; j++) {
            float f = xlv[j] + xrv[j];
            f = (f > 0.0f) ? f : NEG_SLOPE * f;
            part = fmaf(f, av[j], part);
        }
        part += __shfl_xor_sync(0xffffffffu, part, 1);
        part += __shfl_xor_sync(0xffffffffu, part, 2);

        float pe = __expf(part);
        den += pe;
#pragma unroll
        for (int j = 0; j < 16; j++) acc[j] = fmaf(pe, xlv[j], acc[j]);
    }

    float inv = 1.0f / (den + 1e-16f);
    const float* b = bias + dbase;

    __half2 ov[8];
#pragma unroll
    for (int j = 0; j < 8; j++) {
        float v0 = acc[j*2+0] * inv + b[j*2+0];
        float v1 = acc[j*2+1] * inv + b[j*2+1];
        v0 = (v0 > 0.f) ? v0 : (__expf(v0) - 1.0f);
        v1 = (v1 > 0.f) ? v1 : (__expf(v1) - 1.0f);
        ov[j] = __floats2half2_rn(v0, v1);
    }
    uint4* o = (uint4*)(out + (size_t)node * HID + dbase);
    o[0] = *(uint4*)&ov[0];
    o[1] = *(uint4*)&ov[4];
}

// ---------------- fused pool + BN + FC head ----------------
__global__ __launch_bounds__(256) void head_kernel(
    const __half* __restrict__ h,
    const float* __restrict__ gamma, const float* __restrict__ beta,
    const float* __restrict__ mean,  const float* __restrict__ var,
    const float* __restrict__ Wfc,   const float* __restrict__ bfc,
    float* __restrict__ out)
{
    int g = blockIdx.x;
    int j = threadIdx.x;
    __shared__ float s[HID];

    int n0 = d_goff[g], n1 = d_goff[g + 1];
    float s0 = 0.0f, s1 = 0.0f;
    for (int n = n0; n < n1; n++) {
        const __half* row = h + (size_t)n * HID;
        s0 += __half2float(row[j]);
        s1 += __half2float(row[j + 256]);
    }
    s[j]       = (s0 - mean[j])       * rsqrtf(var[j] + BN_EPS)       * gamma[j]       + beta[j];
    s[j + 256] = (s1 - mean[j + 256]) * rsqrtf(var[j + 256] + BN_EPS) * gamma[j + 256] + beta[j + 256];
    __syncthreads();

    float acc = bfc[j];
    for (int k = 0; k < HID; k++) acc = fmaf(s[k], Wfc[(size_t)k * LAT + j], acc);
    out[(size_t)g * LAT + j] = acc;
}

// ---------------- launch ----------------
extern "C" void kernel_launch(void* const* d_in, const int* in_sizes, int n_in,
                              void* d_out, int out_size)
{
    const float* x      = (const float*)d_in[0];
    const int*   ei     = (const int*)d_in[1];
    const int*   batch  = (const int*)d_in[2];
    const float* Wl0    = (const float*)d_in[3];
    const float* bl0    = (const float*)d_in[4];
    const float* Wr0    = (const float*)d_in[5];
    const float* br0    = (const float*)d_in[6];
    const float* att0   = (const float*)d_in[7];
    const float* bias0  = (const float*)d_in[8];
    const float* Wl1    = (const float*)d_in[9];
    const float* bl1    = (const float*)d_in[10];
    const float* Wr1    = (const float*)d_in[11];
    const float* br1    = (const float*)d_in[12];
    const float* att1   = (const float*)d_in[13];
    const float* bias1  = (const float*)d_in[14];
    const float* bn_g   = (const float*)d_in[15];
    const float* bn_b   = (const float*)d_in[16];
    const float* bn_m   = (const float*)d_in[17];
    const float* bn_v   = (const float*)d_in[18];
    const float* Wfc    = (const float*)d_in[19];
    const float* bfc    = (const float*)d_in[20];
    float* out = (float*)d_out;

    const int* src = ei;
    const int* dst = ei + N_EDGES;

    __half *p_xh, *p_xlh, *p_xrh, *p_wt0, *p_wt1;
    int *p_deg;
    cudaGetSymbolAddress((void**)&p_xh, d_xh);
    cudaGetSymbolAddress((void**)&p_xlh, d_xlh);
    cudaGetSymbolAddress((void**)&p_xrh, d_xrh);
    cudaGetSymbolAddress((void**)&p_wt0, d_wt0);
    cudaGetSymbolAddress((void**)&p_wt1, d_wt1);
    cudaGetSymbolAddress((void**)&p_deg, d_deg);

    // once-only resources (created during the pre-capture correctness call)
    static bool inited = false;
    static cudaStream_t s2;
    static cudaEvent_t evFork, evJoin;
    if (!inited) {
        cudaStreamCreateWithFlags(&s2, cudaStreamNonBlocking);
        cudaEventCreateWithFlags(&evFork, cudaEventDisableTiming);
        cudaEventCreateWithFlags(&evJoin, cudaEventDisableTiming);
        cudaFuncSetAttribute(scan_kernel,
                             cudaFuncAttributeMaxDynamicSharedMemorySize, N_NODES * 4);
        inited = true;
    }

    // ---- fork: layer-1 weight transposes + CSR build (all off the critical path)
    cudaEventRecord(evFork, 0);
    cudaStreamWaitEvent(s2, evFork, 0);
    prep1_kernel<<<512, 256, 0, s2>>>(Wl1, Wr1);
    zero_int_kernel<<<(N_NODES + 255) / 256, 256, 0, s2>>>(p_deg, N_NODES);
    hist_kernel<<<(N_EDGES + 255) / 256, 256, 0, s2>>>(dst);
    scan_kernel<<<1, 1024, N_NODES * 4, s2>>>(batch);
    scatter_kernel<<<(N_EDGES + 255) / 256, 256, 0, s2>>>(src, dst);
    cudaEventRecord(evJoin, s2);

    // ---- main stream: conv + layer-0 weight transposes + layer-0 GEMM ----
    prep0_kernel<<<PREP_CONV_BLOCKS + 256, 256>>>(x, Wl0, Wr0);

    dim3 gemmGrid(8, (N_NODES + GBM - 1) / GBM);
    gemm_dual_kernel<<<gemmGrid, 128>>>(p_xh, p_wt0, bl0, br0, p_xlh, p_xrh, N_NODES, IN_DIM);

    // join fork (CSR + wt1) before the gather kernel
    cudaStreamWaitEvent(0, evJoin, 0);

    // ---- layer 0 gather ----
    gat_fused_kernel<<<(N_NODES * 32 + 255) / 256, 256>>>(p_xlh, p_xrh, att0, bias0, p_xh);

    // ---- layer 1 ----
    gemm_dual_kernel<<<gemmGrid, 128>>>(p_xh, p_wt1, bl1, br1, p_xlh, p_xrh, N_NODES, HID);
    gat_fused_kernel<<<(N_NODES * 32 + 255) / 256, 256>>>(p_xlh, p_xrh, att1, bias1, p_xh);

    // ---- fused pool + BN + FC head ----
    head_kernel<<<N_GRAPHS, LAT>>>(p_xh, bn_g, bn_b, bn_m, bn_v, Wfc, bfc, out);
}

// round 17
// speedup vs baseline: 1.1117x; 1.0432x over previous
#include <cuda_runtime.h>
#include <cuda_fp16.h>
#include <cstdint>
#include <math.h>

#define N_NODES 20000
#define N_EDGES 200000
#define N_GRAPHS 128
#define IN_DIM 256
#define HID 512
#define HEADS 8
#define CH 64
#define LAT 256
#define NEG_SLOPE 0.2f
#define BN_EPS 1e-5f

// ---------------- scratch (static device globals; no allocation) ----------------
__device__ __align__(16) __half d_xh [(size_t)N_NODES * HID];   // GEMM A input; later: final h (fp16)
__device__ __align__(16) __half d_xlh[(size_t)N_NODES * HID];   // xl fp16
__device__ __align__(16) __half d_xrh[(size_t)N_NODES * HID];   // xr fp16
__device__ __align__(16) __half d_wt0[(size_t)1024 * 512];      // [Wl0^T; Wr0^T] fp16 [1024, K0]
__device__ __align__(16) __half d_wt1[(size_t)1024 * 512];      // [Wl1^T; Wr1^T] fp16 [1024, K1]
__device__ __align__(16) int   d_deg[N_NODES];
__device__ int   d_off[N_NODES + 1];
__device__ int   d_cursor[N_NODES];
__device__ int   d_csr[N_EDGES];         // stores SRC node id, grouped by dst
__device__ int   d_goff[N_GRAPHS + 1];

// ---------------- async / ldmatrix helpers ----------------
__device__ __forceinline__ void cp_async16(uint32_t dst, const void* src, int srcBytes) {
    asm volatile("cp.async.cg.shared.global [%0], [%1], 16, %2;"
                 :: "r"(dst), "l"(src), "r"(srcBytes));
}
__device__ __forceinline__ void cp_commit() {
    asm volatile("cp.async.commit_group;");
}
template <int NREM>
__device__ __forceinline__ void cp_wait() {
    asm volatile("cp.async.wait_group %0;" :: "n"(NREM));
}
__device__ __forceinline__ void ldsm_x4(uint32_t (&r)[4], uint32_t addr) {
    asm volatile("ldmatrix.sync.aligned.m8n8.x4.shared.b16 {%0,%1,%2,%3}, [%4];"
                 : "=r"(r[0]), "=r"(r[1]), "=r"(r[2]), "=r"(r[3]) : "r"(addr));
}

// ---------------- small utility kernels ----------------
__global__ void zero_int_kernel(int* p, int n) {
    int i = blockIdx.x * blockDim.x + threadIdx.x;
    if (i < n) p[i] = 0;
}

__global__ void hist_kernel(const int* __restrict__ dst) {
    int e = blockIdx.x * blockDim.x + threadIdx.x;
    if (e < N_EDGES) atomicAdd(&d_deg[dst[e]], 1);
}

// single-block scan: smem-staged, coalesced global access.
__global__ void scan_kernel(const int* __restrict__ batch) {
    extern __shared__ int sdeg[];
    __shared__ int warpsum[33];
    int t = threadIdx.x;

    if (t <= N_GRAPHS) {
        int lo = 0, hi = N_NODES;
        while (lo < hi) {
            int mid = (lo + hi) >> 1;
            if (batch[mid] < t) lo = mid + 1; else hi = mid;
        }
        d_goff[t] = lo;
    }

    for (int i = t; i < N_NODES / 4; i += 1024)
        ((int4*)sdeg)[i] = ((const int4*)d_deg)[i];
    __syncthreads();

    const int base = t * 20;
    int s = 0;
    if (base < N_NODES)
#pragma unroll
        for (int i = 0; i < 20; i++) s += sdeg[base + i];

    int incl = s;
    int lane = t & 31;
#pragma unroll
    for (int o = 1; o < 32; o <<= 1) {
        int u = __shfl_up_sync(0xffffffffu, incl, o);
        if (lane >= o) incl += u;
    }
    if (lane == 31) warpsum[t >> 5] = incl;
    __syncthreads();
    if (t < 32) {
        int w = warpsum[t];
        int wi = w;
#pragma unroll
        for (int o = 1; o < 32; o <<= 1) {
            int u = __shfl_up_sync(0xffffffffu, wi, o);
            if (t >= o) wi += u;
        }
        warpsum[t] = wi - w;
        if (t == 31) warpsum[32] = wi;
    }
    __syncthreads();

    if (base < N_NODES) {
        int run = warpsum[t >> 5] + (incl - s);
#pragma unroll
        for (int i = 0; i < 20; i++) {
            int v = sdeg[base + i];
            sdeg[base + i] = run;
            run += v;
        }
    }
    __syncthreads();

    for (int i = t; i < N_NODES / 4; i += 1024) {
        int4 v = ((int4*)sdeg)[i];
        ((int4*)d_off)[i] = v;
        ((int4*)d_cursor)[i] = v;
    }
    if (t == 0) d_off[N_NODES] = warpsum[32];
}

__global__ void scatter_kernel(const int* __restrict__ src, const int* __restrict__ dst) {
    int e = blockIdx.x * blockDim.x + threadIdx.x;
    if (e < N_EDGES) {
        int p = atomicAdd(&d_cursor[dst[e]], 1);
        d_csr[p] = src[e];
    }
}

// ---------------- shared weight-transpose body ----------------
__device__ __forceinline__ void wtrans_tile(const float* W, __half* Wt, int K, int bx, int by) {
    __shared__ float tile[32][33];
    int n0 = bx * 32;
    int k0 = by * 32;
    int tx = threadIdx.x & 31, ty = threadIdx.x >> 5;
#pragma unroll
    for (int j = 0; j < 32; j += 8)
        tile[ty + j][tx] = W[(size_t)(k0 + ty + j) * HID + n0 + tx];
    __syncthreads();
#pragma unroll
    for (int j = 0; j < 32; j += 8)
        Wt[(size_t)(n0 + ty + j) * K + k0 + tx] = __float2half_rn(tile[tx][ty + j]);
}

// prep0: x->fp16 conversion + layer-0 weight transposes (critical path for GEMM0)
#define PREP_CONV_BLOCKS 5000
__global__ __launch_bounds__(256) void prep0_kernel(
    const float* __restrict__ x,
    const float* __restrict__ Wl0, const float* __restrict__ Wr0)
{
    int b = blockIdx.x;
    if (b < PREP_CONV_BLOCKS) {
        int i = b * 256 + threadIdx.x;
        float4 v = ((const float4*)x)[i];
        __half2* d = (__half2*)d_xh;
        d[i * 2 + 0] = __floats2half2_rn(v.x, v.y);
        d[i * 2 + 1] = __floats2half2_rn(v.z, v.w);
        return;
    }
    int m = b - PREP_CONV_BLOCKS;
    int mat = m >> 7;
    int tb = m & 127;
    wtrans_tile(mat ? Wr0 : Wl0, d_wt0 + (size_t)mat * 512 * IN_DIM,
                IN_DIM, tb & 15, tb >> 4);
}

// prep1: layer-1 weight transposes (fork stream; needed by GEMM1 only)
__global__ __launch_bounds__(256) void prep1_kernel(
    const float* __restrict__ Wl1, const float* __restrict__ Wr1)
{
    int m = blockIdx.x;
    int mat = m >> 8;
    int tb = m & 255;
    wtrans_tile(mat ? Wr1 : Wl1, d_wt1 + (size_t)mat * 512 * HID,
                HID, tb & 15, tb >> 4);
}

// ---------------- dual-output fp16 GEMM (2-stage cp.async + ldmatrix) ------------
// R12-proven: 128 threads, occupancy 2, 128x128 tiles.
#define GBM 128
#define HBK 32
#define SSTR 40   // halves per smem row (conflict-free for STS.128 and LDSM)

__global__ __launch_bounds__(128, 2) void gemm_dual_kernel(
    const __half* __restrict__ A, const __half* __restrict__ Bt,
    const float* __restrict__ biasL, const float* __restrict__ biasR,
    __half* __restrict__ Cl, __half* __restrict__ Cr,
    int N, int K)
{
    __shared__ __half As[2][GBM * SSTR];
    __shared__ __half Bs[2][GBM * SSTR];

    const int tid  = threadIdx.x;
    const int lane = tid & 31;
    const int warp = tid >> 5;
    const int wm = warp & 1;
    const int wn = warp >> 1;
    const int rowBase = blockIdx.y * GBM;
    const int colBase = blockIdx.x * 128;        // 0..1023 over concat
    const int g = lane >> 2;
    const int q = lane & 3;
    const int nt = K / HBK;

    const uint32_t asb = (uint32_t)__cvta_generic_to_shared(&As[0][0]);
    const uint32_t bsb = (uint32_t)__cvta_generic_to_shared(&Bs[0][0]);
    const uint32_t BUFB = GBM * SSTR * 2;

    const int lr = tid >> 2;
    const int lc = (tid & 3) * 8;

    float acc[4][8][4];
#pragma unroll
    for (int i = 0; i < 4; i++)
#pragma unroll
        for (int j = 0; j < 8; j++)
#pragma unroll
            for (int p = 0; p < 4; p++) acc[i][j][p] = 0.0f;

    // prefetch tile 0
    {
#pragma unroll
        for (int i = 0; i < 4; i++) {
            int r = rowBase + lr + 32 * i;
            int rs = (r < N) ? r : 0;
            cp_async16(asb + ((lr + 32 * i) * SSTR + lc) * 2,
                       A + (size_t)rs * K + lc, (r < N) ? 16 : 0);
            int br = colBase + lr + 32 * i;
            cp_async16(bsb + ((lr + 32 * i) * SSTR + lc) * 2,
                       Bt + (size_t)br * K + lc, 16);
        }
        cp_commit();
    }

    for (int t = 0; t < nt; t++) {
        int buf = t & 1;
        if (t + 1 < nt) {
            int kb = (t + 1) * HBK;
            uint32_t aoff = asb + (buf ^ 1) * BUFB;
            uint32_t boff = bsb + (buf ^ 1) * BUFB;
#pragma unroll
            for (int i = 0; i < 4; i++) {
                int r = rowBase + lr + 32 * i;
                int rs = (r < N) ? r : 0;
                cp_async16(aoff + ((lr + 32 * i) * SSTR + lc) * 2,
                           A + (size_t)rs * K + kb + lc, (r < N) ? 16 : 0);
                int br = colBase + lr + 32 * i;
                cp_async16(boff + ((lr + 32 * i) * SSTR + lc) * 2,
                           Bt + (size_t)br * K + kb + lc, 16);
            }
            cp_commit();
            cp_wait<1>();
        } else {
            cp_wait<0>();
        }
        __syncthreads();

        uint32_t abase = asb + buf * BUFB;
        uint32_t bbase = bsb + buf * BUFB;
        const int arow = wm * 64 + (lane & 15);
        const int ax   = ((lane >> 4) << 3);
        const int bnx  = ((lane >> 4) & 1) * 8 + (lane & 7);
        const int bkx  = ((lane >> 3) & 1) * 8;

#pragma unroll
        for (int kk = 0; kk < 2; kk++) {
            const int kh0 = kk * 16;
            uint32_t af[4][4];
#pragma unroll
            for (int im = 0; im < 4; im++)
                ldsm_x4(af[im], abase + ((arow + im * 16) * SSTR + kh0 + ax) * 2);
            uint32_t bf[8][2];
#pragma unroll
            for (int j = 0; j < 8; j += 2) {
                uint32_t r4[4];
                ldsm_x4(r4, bbase + ((wn * 64 + j * 8 + bnx) * SSTR + kh0 + bkx) * 2);
                bf[j][0] = r4[0]; bf[j][1] = r4[1];
                bf[j + 1][0] = r4[2]; bf[j + 1][1] = r4[3];
            }
#pragma unroll
            for (int im = 0; im < 4; im++)
#pragma unroll
                for (int in = 0; in < 8; in++) {
                    asm volatile(
                        "mma.sync.aligned.m16n8k16.row.col.f32.f16.f16.f32 "
                        "{%0,%1,%2,%3}, {%4,%5,%6,%7}, {%8,%9}, {%0,%1,%2,%3};"
                        : "+f"(acc[im][in][0]), "+f"(acc[im][in][1]),
                          "+f"(acc[im][in][2]), "+f"(acc[im][in][3])
                        : "r"(af[im][0]), "r"(af[im][1]), "r"(af[im][2]), "r"(af[im][3]),
                          "r"(bf[in][0]), "r"(bf[in][1]));
                }
        }
        __syncthreads();
    }

    // ---- epilogue ----
    const bool left = (colBase < HID);
    const float* bias = left ? biasL : biasR;
    __half* C = left ? Cl : Cr;
    const int cadj = left ? colBase : (colBase - HID);

    float bv0[8], bv1[8];
#pragma unroll
    for (int in = 0; in < 8; in++) {
        int c = cadj + wn * 64 + in * 8 + 2 * q;
        bv0[in] = bias[c];
        bv1[in] = bias[c + 1];
    }
#pragma unroll
    for (int im = 0; im < 4; im++) {
        int r0 = rowBase + wm * 64 + im * 16 + g;
        int r1 = r0 + 8;
#pragma unroll
        for (int in = 0; in < 8; in++) {
            int c = cadj + wn * 64 + in * 8 + 2 * q;
            if (r0 < N)
                *(__half2*)(C + (size_t)r0 * HID + c) =
                    __floats2half2_rn(acc[im][in][0] + bv0[in], acc[im][in][1] + bv1[in]);
            if (r1 < N)
                *(__half2*)(C + (size_t)r1 * HID + c) =
                    __floats2half2_rn(acc[im][in][2] + bv0[in], acc[im][in][3] + bv1[in]);
        }
    }
}

// ---------------- fused GAT edge+softmax+aggregate (shift-free softmax) ----------
// 64-thread blocks (2 warps): small retirement quantum -> less degree-imbalance
// loss; 32 blocks/SM keeps full 2048-thread occupancy.
__global__ __launch_bounds__(64) void gat_fused_kernel(
    const __half* __restrict__ xl16, const __half* __restrict__ xr16,
    const float* __restrict__ att, const float* __restrict__ bias,
    __half* __restrict__ out)
{
    int node = (blockIdx.x * blockDim.x + threadIdx.x) >> 5;
    if (node >= N_NODES) return;
    int lane = threadIdx.x & 31;
    int dbase = lane * 16;

    float xrv[16], av[16];
    {
        const uint4* pxr = (const uint4*)(xr16 + (size_t)node * HID + dbase);
        uint4 u0 = pxr[0], u1 = pxr[1];
        const __half2* h0 = (const __half2*)&u0;
        const __half2* h1 = (const __half2*)&u1;
#pragma unroll
        for (int j = 0; j < 4; j++) {
            float2 f0 = __half22float2(h0[j]);
            xrv[j*2+0] = f0.x; xrv[j*2+1] = f0.y;
            float2 f1 = __half22float2(h1[j]);
            xrv[8+j*2+0] = f1.x; xrv[8+j*2+1] = f1.y;
        }
        const float4* pat = (const float4*)(att + dbase);
#pragma unroll
        for (int j = 0; j < 4; j++) {
            float4 b = pat[j];
            av[j*4+0] = b.x; av[j*4+1] = b.y; av[j*4+2] = b.z; av[j*4+3] = b.w;
        }
    }

    float den = 0.0f;
    float acc[16];
#pragma unroll
    for (int j = 0; j < 16; j++) acc[j] = 0.0f;

    int r0 = d_off[node], r1 = d_off[node + 1];
    for (int i = r0; i < r1; i++) {
        int s = d_csr[i];
        const uint4* p = (const uint4*)(xl16 + (size_t)s * HID + dbase);
        uint4 u0 = p[0], u1 = p[1];
        float xlv[16];
        {
            const __half2* h0 = (const __half2*)&u0;
            const __half2* h1 = (const __half2*)&u1;
#pragma unroll
            for (int j = 0; j < 4; j++) {
                float2 f0 = __half22float2(h0[j]);
                xlv[j*2+0] = f0.x; xlv[j*2+1] = f0.y;
                float2 f1 = __half22float2(h1[j]);
                xlv[8+j*2+0] = f1.x; xlv[8+j*2+1] = f1.y;
            }
        }
        float part = 0.0f;
#pragma unroll
        for (int j = 0; j < 16; j++) {
            float f = xlv[j] + xrv[j];
            f = (f > 0.0f) ? f : NEG_SLOPE * f;
            part = fmaf(f, av[j], part);
        }
        part += __shfl_xor_sync(0xffffffffu, part, 1);
        part += __shfl_xor_sync(0xffffffffu, part, 2);

        float pe = __expf(part);
        den += pe;
#pragma unroll
        for (int j = 0; j < 16; j++) acc[j] = fmaf(pe, xlv[j], acc[j]);
    }

    float inv = 1.0f / (den + 1e-16f);
    const float* b = bias + dbase;

    __half2 ov[8];
#pragma unroll
    for (int j = 0; j < 8; j++) {
        float v0 = acc[j*2+0] * inv + b[j*2+0];
        float v1 = acc[j*2+1] * inv + b[j*2+1];
        v0 = (v0 > 0.f) ? v0 : (__expf(v0) - 1.0f);
        v1 = (v1 > 0.f) ? v1 : (__expf(v1) - 1.0f);
        ov[j] = __floats2half2_rn(v0, v1);
    }
    uint4* o = (uint4*)(out + (size_t)node * HID + dbase);
    o[0] = *(uint4*)&ov[0];
    o[1] = *(uint4*)&ov[4];
}

// ---------------- fused pool + BN + FC head ----------------
__global__ __launch_bounds__(256) void head_kernel(
    const __half* __restrict__ h,
    const float* __restrict__ gamma, const float* __restrict__ beta,
    const float* __restrict__ mean,  const float* __restrict__ var,
    const float* __restrict__ Wfc,   const float* __restrict__ bfc,
    float* __restrict__ out)
{
    int g = blockIdx.x;
    int j = threadIdx.x;
    __shared__ float s[HID];

    int n0 = d_goff[g], n1 = d_goff[g + 1];
    float s0 = 0.0f, s1 = 0.0f;
    for (int n = n0; n < n1; n++) {
        const __half* row = h + (size_t)n * HID;
        s0 += __half2float(row[j]);
        s1 += __half2float(row[j + 256]);
    }
    s[j]       = (s0 - mean[j])       * rsqrtf(var[j] + BN_EPS)       * gamma[j]       + beta[j];
    s[j + 256] = (s1 - mean[j + 256]) * rsqrtf(var[j + 256] + BN_EPS) * gamma[j + 256] + beta[j + 256];
    __syncthreads();

    float acc = bfc[j];
    for (int k = 0; k < HID; k++) acc = fmaf(s[k], Wfc[(size_t)k * LAT + j], acc);
    out[(size_t)g * LAT + j] = acc;
}

// ---------------- launch ----------------
extern "C" void kernel_launch(void* const* d_in, const int* in_sizes, int n_in,
                              void* d_out, int out_size)
{
    const float* x      = (const float*)d_in[0];
    const int*   ei     = (const int*)d_in[1];
    const int*   batch  = (const int*)d_in[2];
    const float* Wl0    = (const float*)d_in[3];
    const float* bl0    = (const float*)d_in[4];
    const float* Wr0    = (const float*)d_in[5];
    const float* br0    = (const float*)d_in[6];
    const float* att0   = (const float*)d_in[7];
    const float* bias0  = (const float*)d_in[8];
    const float* Wl1    = (const float*)d_in[9];
    const float* bl1    = (const float*)d_in[10];
    const float* Wr1    = (const float*)d_in[11];
    const float* br1    = (const float*)d_in[12];
    const float* att1   = (const float*)d_in[13];
    const float* bias1  = (const float*)d_in[14];
    const float* bn_g   = (const float*)d_in[15];
    const float* bn_b   = (const float*)d_in[16];
    const float* bn_m   = (const float*)d_in[17];
    const float* bn_v   = (const float*)d_in[18];
    const float* Wfc    = (const float*)d_in[19];
    const float* bfc    = (const float*)d_in[20];
    float* out = (float*)d_out;

    const int* src = ei;
    const int* dst = ei + N_EDGES;

    __half *p_xh, *p_xlh, *p_xrh, *p_wt0, *p_wt1;
    int *p_deg;
    cudaGetSymbolAddress((void**)&p_xh, d_xh);
    cudaGetSymbolAddress((void**)&p_xlh, d_xlh);
    cudaGetSymbolAddress((void**)&p_xrh, d_xrh);
    cudaGetSymbolAddress((void**)&p_wt0, d_wt0);
    cudaGetSymbolAddress((void**)&p_wt1, d_wt1);
    cudaGetSymbolAddress((void**)&p_deg, d_deg);

    // once-only resources (created during the pre-capture correctness call)
    static bool inited = false;
    static cudaStream_t s2;
    static cudaEvent_t evFork, evJoin;
    if (!inited) {
        cudaStreamCreateWithFlags(&s2, cudaStreamNonBlocking);
        cudaEventCreateWithFlags(&evFork, cudaEventDisableTiming);
        cudaEventCreateWithFlags(&evJoin, cudaEventDisableTiming);
        cudaFuncSetAttribute(scan_kernel,
                             cudaFuncAttributeMaxDynamicSharedMemorySize, N_NODES * 4);
        inited = true;
    }

    // ---- fork: layer-1 weight transposes + CSR build (off the critical path) ----
    cudaEventRecord(evFork, 0);
    cudaStreamWaitEvent(s2, evFork, 0);
    prep1_kernel<<<512, 256, 0, s2>>>(Wl1, Wr1);
    zero_int_kernel<<<(N_NODES + 255) / 256, 256, 0, s2>>>(p_deg, N_NODES);
    hist_kernel<<<(N_EDGES + 255) / 256, 256, 0, s2>>>(dst);
    scan_kernel<<<1, 1024, N_NODES * 4, s2>>>(batch);
    scatter_kernel<<<(N_EDGES + 255) / 256, 256, 0, s2>>>(src, dst);
    cudaEventRecord(evJoin, s2);

    // ---- main stream: conv + layer-0 weight transposes + layer-0 GEMM ----
    prep0_kernel<<<PREP_CONV_BLOCKS + 256, 256>>>(x, Wl0, Wr0);

    dim3 gemmGrid(8, (N_NODES + GBM - 1) / GBM);
    gemm_dual_kernel<<<gemmGrid, 128>>>(p_xh, p_wt0, bl0, br0, p_xlh, p_xrh, N_NODES, IN_DIM);

    // join fork (CSR + wt1) before the gather kernel
    cudaStreamWaitEvent(0, evJoin, 0);

    // ---- layer 0 gather (64-thread blocks) ----
    gat_fused_kernel<<<(N_NODES * 32 + 63) / 64, 64>>>(p_xlh, p_xrh, att0, bias0, p_xh);

    // ---- layer 1 ----
    gemm_dual_kernel<<<gemmGrid, 128>>>(p_xh, p_wt1, bl1, br1, p_xlh, p_xrh, N_NODES, HID);
    gat_fused_kernel<<<(N_NODES * 32 + 63) / 64, 64>>>(p_xlh, p_xrh, att1, bias1, p_xh);

    // ---- fused pool + BN + FC head ----
    head_kernel<<<N_GRAPHS, LAT>>>(p_xh, bn_g, bn_b, bn_m, bn_v, Wfc, bfc, out);
}